// round 1
// baseline (speedup 1.0000x reference)
#include <cuda_runtime.h>
#include <math.h>

// GraphCut loss:
//   sim = (F @ F^T) / 0.2 ; m_i = max_j sim_ij ; kernel = exp(sim - m_i)
//   neg_sum_i = sum_{label_j != label_i} kernel_ij   (diag auto-excluded: same label)
//   pos_cnt_i = hist[label_i] - 1
//   out = sum_{iou_i >= 0.5} (neg_sum_i / pos_cnt_i) / count(iou >= 0.5)
//
// Online-softmax single pass over the 8192x8192 sim matrix; 128 CTAs x 64 rows.

#define MD 8192
#define KD 128
#define NCLS 20
#define BM 64
#define BN 64
#define NT 256
#define NTILES (MD / BN)
#define INV_TEMP 5.0f

__device__ float g_negsum[MD];
__device__ int   g_hist[NCLS];
__device__ float g_featT[(size_t)KD * MD];   // 4 MB scratch: features transposed [K][M]

// ---------------------------------------------------------------- transpose
__global__ void k_transpose(const float* __restrict__ feat) {
    __shared__ float tile[32][33];
    int m0 = blockIdx.x * 32;
    int k0 = blockIdx.y * 32;
    int x = threadIdx.x, y = threadIdx.y;
#pragma unroll
    for (int i = 0; i < 32; i += 8)
        tile[y + i][x] = feat[(size_t)(m0 + y + i) * KD + (k0 + x)];
    __syncthreads();
#pragma unroll
    for (int i = 0; i < 32; i += 8)
        g_featT[(size_t)(k0 + y + i) * MD + (m0 + x)] = tile[x][y + i];
}

// ---------------------------------------------------------------- histogram
__global__ void k_hist_zero() {
    if (threadIdx.x < NCLS) g_hist[threadIdx.x] = 0;
}

__global__ void k_hist(const int* __restrict__ labels) {
    int i = blockIdx.x * blockDim.x + threadIdx.x;
    if (i < MD) {
        int l = labels[i];
        l = l < 0 ? 0 : (l >= NCLS ? NCLS - 1 : l);   // defensive clamp
        atomicAdd(&g_hist[l], 1);
    }
}

// ---------------------------------------------------- fused GEMM + softmax
// smem: As [KD][BM] (k-major, i contiguous) + Bs [KD][BN] = 64 KB dynamic.
// Threads 16x16; each thread owns a 4x4 micro-tile.
__global__ void __launch_bounds__(NT) k_main(const int* __restrict__ labels) {
    extern __shared__ float smem[];
    float4* As4 = (float4*)smem;               // [KD][BM/4] float4
    float4* Bs4 = (float4*)(smem + KD * BM);   // [KD][BN/4] float4
    __shared__ int lblB[BN];

    int tid = threadIdx.x;
    int tx = tid & 15;          // col group (4 cols)
    int ty = tid >> 4;          // row group (4 rows)
    int i0 = blockIdx.x * BM;

    int j4    = tid & 15;       // float4 lane within a k-row
    int kbase = tid >> 4;       // 0..15

    // Load A tile once: As[k][i0..i0+63]
#pragma unroll
    for (int it = 0; it < 8; it++) {
        int k = kbase + 16 * it;
        As4[k * 16 + j4] = *(const float4*)&g_featT[(size_t)k * MD + i0 + j4 * 4];
    }

    int   myLbl[4];
    float mrow[4], srow[4];
#pragma unroll
    for (int r = 0; r < 4; r++) {
        myLbl[r] = labels[i0 + ty * 4 + r];
        mrow[r]  = -INFINITY;
        srow[r]  = 0.0f;
    }

    // Prefetch tile 0 into registers, store, sync (covers As stores too).
    float4 pre[8];
#pragma unroll
    for (int it = 0; it < 8; it++) {
        int k = kbase + 16 * it;
        pre[it] = *(const float4*)&g_featT[(size_t)k * MD + j4 * 4];
    }
    int lblPre = (tid < BN) ? labels[tid] : 0;
#pragma unroll
    for (int it = 0; it < 8; it++) {
        int k = kbase + 16 * it;
        Bs4[k * 16 + j4] = pre[it];
    }
    if (tid < BN) lblB[tid] = lblPre;
    __syncthreads();

    for (int t = 0; t < NTILES; t++) {
        // Prefetch next tile into registers (LDG latency hidden by compute)
        if (t + 1 < NTILES) {
            int j0n = (t + 1) * BN;
#pragma unroll
            for (int it = 0; it < 8; it++) {
                int k = kbase + 16 * it;
                pre[it] = *(const float4*)&g_featT[(size_t)k * MD + j0n + j4 * 4];
            }
            if (tid < BN) lblPre = labels[j0n + tid];
        }

        float acc[16];
#pragma unroll
        for (int q = 0; q < 16; q++) acc[q] = 0.0f;

#pragma unroll 8
        for (int k = 0; k < KD; k++) {
            float4 a4 = As4[k * 16 + ty];   // 4 rows (broadcast within ty group)
            float4 b4 = Bs4[k * 16 + tx];   // 4 cols
            acc[0]  += a4.x * b4.x;  acc[1]  += a4.x * b4.y;
            acc[2]  += a4.x * b4.z;  acc[3]  += a4.x * b4.w;
            acc[4]  += a4.y * b4.x;  acc[5]  += a4.y * b4.y;
            acc[6]  += a4.y * b4.z;  acc[7]  += a4.y * b4.w;
            acc[8]  += a4.z * b4.x;  acc[9]  += a4.z * b4.y;
            acc[10] += a4.z * b4.z;  acc[11] += a4.z * b4.w;
            acc[12] += a4.w * b4.x;  acc[13] += a4.w * b4.y;
            acc[14] += a4.w * b4.z;  acc[15] += a4.w * b4.w;
        }

        // Online softmax epilogue. Row r is owned by the 16 lanes of one ty group.
        int lb0 = lblB[tx * 4 + 0];
        int lb1 = lblB[tx * 4 + 1];
        int lb2 = lblB[tx * 4 + 2];
        int lb3 = lblB[tx * 4 + 3];

#pragma unroll
        for (int r = 0; r < 4; r++) {
            float s0 = acc[r * 4 + 0] * INV_TEMP;
            float s1 = acc[r * 4 + 1] * INV_TEMP;
            float s2 = acc[r * 4 + 2] * INV_TEMP;
            float s3 = acc[r * 4 + 3] * INV_TEMP;
            // max is over ALL columns (incl. diag & positives), matching reference
            float tmax = fmaxf(fmaxf(s0, s1), fmaxf(s2, s3));
#pragma unroll
            for (int off = 8; off > 0; off >>= 1)
                tmax = fmaxf(tmax, __shfl_xor_sync(0xffffffffu, tmax, off));
            float newm = fmaxf(mrow[r], tmax);
            float p = 0.0f;
            if (lb0 != myLbl[r]) p += expf(s0 - newm);
            if (lb1 != myLbl[r]) p += expf(s1 - newm);
            if (lb2 != myLbl[r]) p += expf(s2 - newm);
            if (lb3 != myLbl[r]) p += expf(s3 - newm);
#pragma unroll
            for (int off = 8; off > 0; off >>= 1)
                p += __shfl_xor_sync(0xffffffffu, p, off);
            srow[r] = srow[r] * expf(mrow[r] - newm) + p;
            mrow[r] = newm;
        }

        __syncthreads();   // everyone done reading Bs/lblB
        if (t + 1 < NTILES) {
#pragma unroll
            for (int it = 0; it < 8; it++) {
                int k = kbase + 16 * it;
                Bs4[k * 16 + j4] = pre[it];
            }
            if (tid < BN) lblB[tid] = lblPre;
            __syncthreads();
        }
    }

    if (tx == 0) {
#pragma unroll
        for (int r = 0; r < 4; r++)
            g_negsum[i0 + ty * 4 + r] = srow[r];
    }
}

// ---------------------------------------------------------------- finalize
__global__ void k_final(const int* __restrict__ labels,
                        const float* __restrict__ ious,
                        float* __restrict__ out) {
    __shared__ float ssum[256];
    __shared__ float scnt[256];
    int tid = threadIdx.x;
    float sum = 0.0f, cnt = 0.0f;
    for (int i = tid; i < MD; i += 256) {
        if (ious[i] >= 0.5f) {
            int l = labels[i];
            l = l < 0 ? 0 : (l >= NCLS ? NCLS - 1 : l);
            float pc = (float)(g_hist[l] - 1);
            sum += g_negsum[i] / pc;   // matches reference semantics (incl. 0/0 -> nan)
            cnt += 1.0f;
        }
    }
    ssum[tid] = sum;
    scnt[tid] = cnt;
    __syncthreads();
    for (int s = 128; s > 0; s >>= 1) {
        if (tid < s) { ssum[tid] += ssum[tid + s]; scnt[tid] += scnt[tid + s]; }
        __syncthreads();
    }
    if (tid == 0) out[0] = ssum[0] / scnt[0];
}

// ---------------------------------------------------------------- launch
extern "C" void kernel_launch(void* const* d_in, const int* in_sizes, int n_in,
                              void* d_out, int out_size) {
    const float* feat   = (const float*)d_in[0];
    const int*   labels = (const int*)  d_in[1];
    const float* ious   = (const float*)d_in[2];
    float*       out    = (float*)d_out;
    (void)in_sizes; (void)n_in; (void)out_size;

    const int smem_bytes = (KD * BM + KD * BN) * (int)sizeof(float);   // 64 KB
    cudaFuncSetAttribute(k_main, cudaFuncAttributeMaxDynamicSharedMemorySize, smem_bytes);

    k_transpose<<<dim3(MD / 32, KD / 32), dim3(32, 8)>>>(feat);
    k_hist_zero<<<1, 32>>>();
    k_hist<<<MD / 256, 256>>>(labels);
    k_main<<<MD / BM, NT, smem_bytes>>>(labels);
    k_final<<<1, 256>>>(labels, ious, out);
}

// round 3
// speedup vs baseline: 2.4940x; 2.4940x over previous
#include <cuda_runtime.h>
#include <cuda_bf16.h>
#include <math.h>
#include <stdint.h>

// ============================================================================
// GraphCut loss. GEMM via mma.sync bf16 (HMMA path, plain sm_100-compatible),
// fused exact fp32 online-softmax epilogue, per-thread (m,p) running state.
//   sim = (F F^T)/0.2 ; m_i = rowmax ; neg_i = sum_{lbl_j != lbl_i} exp(s-m_i)
//   out = mean over {iou>=0.5} of neg_i / (hist[lbl_i]-1)
// Features pre-scaled by sqrt(5) so accumulators are already "s" values.
// Exactness: exp(x)==0 exactly for x<=-105; fast path only skips provably-zero
// terms; all cross-partial combines are exact log-sum-exp merges.
// ============================================================================

#define MD 8192
#define KD 128
#define NCLS 20
#define TN 128
#define NHALF 4096
#define NTILES (NHALF / TN)     // 32
#define NTHREADS 256
#define THRESH 105.0f

__device__ __align__(16) __nv_bfloat16 g_featB[(size_t)MD * KD];  // 2MB, *sqrt(5)
__device__ float2 g_pm[2 * MD];   // per-half (rowmax, partial neg_sum)
__device__ int    g_hist[NCLS];

// ---------------------------------------------------------------- helpers
__device__ __forceinline__ uint32_t smem_u32(const void* p) {
    uint32_t a;
    asm("{ .reg .u64 t; cvta.to.shared.u64 t, %1; cvt.u32.u64 %0, t; }" : "=r"(a) : "l"(p));
    return a;
}
#define CP_ASYNC16(dst, src) \
    asm volatile("cp.async.cg.shared.global [%0], [%1], 16;" :: "r"(dst), "l"(src) : "memory")
#define CP_COMMIT() asm volatile("cp.async.commit_group;" ::: "memory")
#define CP_WAIT0()  asm volatile("cp.async.wait_group 0;" ::: "memory")
#define LDSM_X4(r0, r1, r2, r3, a) \
    asm volatile("ldmatrix.sync.aligned.m8n8.x4.shared.b16 {%0,%1,%2,%3}, [%4];" \
                 : "=r"(r0), "=r"(r1), "=r"(r2), "=r"(r3) : "r"(a))
#define MMA16816(c, a0, a1, a2, a3, b0, b1) \
    asm volatile("mma.sync.aligned.m16n8k16.row.col.f32.bf16.bf16.f32 " \
                 "{%0,%1,%2,%3},{%4,%5,%6,%7},{%8,%9},{%0,%1,%2,%3};" \
                 : "+f"((c)[0]), "+f"((c)[1]), "+f"((c)[2]), "+f"((c)[3]) \
                 : "r"(a0), "r"(a1), "r"(a2), "r"(a3), "r"(b0), "r"(b1))

// ---------------------------------------------------------------- convert
__global__ void k_convert(const float* __restrict__ feat) {
    const float SC = 2.23606797749979f;   // sqrt(5) = sqrt(1/TEMPERATURE)
    int i = (blockIdx.x * 256 + threadIdx.x) * 8;
    float4 f0 = *(const float4*)&feat[i];
    float4 f1 = *(const float4*)&feat[i + 4];
    union { __nv_bfloat16 h[8]; uint4 u; } U;
    U.h[0] = __float2bfloat16(f0.x * SC); U.h[1] = __float2bfloat16(f0.y * SC);
    U.h[2] = __float2bfloat16(f0.z * SC); U.h[3] = __float2bfloat16(f0.w * SC);
    U.h[4] = __float2bfloat16(f1.x * SC); U.h[5] = __float2bfloat16(f1.y * SC);
    U.h[6] = __float2bfloat16(f1.z * SC); U.h[7] = __float2bfloat16(f1.w * SC);
    *(uint4*)&g_featB[i] = U.u;
}

// ---------------------------------------------------------------- histogram
__global__ void k_hist_zero() { if (threadIdx.x < NCLS) g_hist[threadIdx.x] = 0; }
__global__ void k_hist(const int* __restrict__ labels) {
    int i = blockIdx.x * blockDim.x + threadIdx.x;
    if (i < MD) {
        int l = labels[i];
        l = l < 0 ? 0 : (l >= NCLS ? NCLS - 1 : l);
        atomicAdd(&g_hist[l], 1);
    }
}

// ---------------------------------------------------------------- main kernel
// smem tile layout: 128 rows x 256B; 16B granule at (row, c16) stored at
// row*256 + ((c16 ^ (row&7))<<4)  -> conflict-free ldmatrix.
__global__ void __launch_bounds__(NTHREADS, 1)
k_tensor(const int* __restrict__ labels) {
    extern __shared__ char dsm[];
    __shared__ float2 s_red[128][4];

    char* A_s  = dsm;                    // 32KB
    char* B_s  = dsm + 32768;            // 2 x 32KB
    int*  sLbl = (int*)(dsm + 98304);    // 16KB
    uint32_t A_u = smem_u32(A_s);
    uint32_t B_u = smem_u32(B_s);

    int tid  = threadIdx.x;
    int lane = tid & 31;
    int wid  = tid >> 5;
    int wm   = wid >> 2;                 // 0..1 : row block of 64
    int wn   = wid & 3;                  // 0..3 : col block of 32
    int r    = blockIdx.x >> 1;
    int h    = blockIdx.x & 1;
    int i0   = r * 128;
    int j0   = h * NHALF;

    // ---- prologue fills ----
    {   // A tile: rows i0..i0+127 (direct)
#pragma unroll
        for (int v = 0; v < 8; v++) {
            int idx = tid + v * NTHREADS;          // 0..2047
            int row = idx >> 4, c16 = idx & 15;
            uint4 val = *(const uint4*)&g_featB[(size_t)(i0 + row) * KD + c16 * 8];
            *(uint4*)(A_s + row * 256 + (((c16 ^ (row & 7)) << 4))) = val;
        }
        // B tile 0 via cp.async
#pragma unroll
        for (int v = 0; v < 8; v++) {
            int idx = tid + v * NTHREADS;
            int row = idx >> 4, c16 = idx & 15;
            CP_ASYNC16(B_u + row * 256 + ((c16 ^ (row & 7)) << 4),
                       &g_featB[(size_t)(j0 + row) * KD + c16 * 8]);
        }
        CP_COMMIT();
#pragma unroll
        for (int v = tid; v < NHALF / 4; v += NTHREADS)
            ((int4*)sLbl)[v] = ((const int4*)(labels + j0))[v];
    }

    // my row labels: 8 row slots (mt 0..3, hh 0..1), row = wm*64+mt*16+hh*8+lane/4
    int myLbl[8];
#pragma unroll
    for (int mt = 0; mt < 4; mt++)
#pragma unroll
        for (int hh = 0; hh < 2; hh++)
            myLbl[mt * 2 + hh] = labels[i0 + wm * 64 + mt * 16 + hh * 8 + (lane >> 2)];

    // ldmatrix per-lane address precompute
    int q  = lane >> 3;                  // matrix id 0..3
    int kh = q >> 1;                     // k-half select
    uint32_t aBase[4]; int aRx[4];
#pragma unroll
    for (int mt = 0; mt < 4; mt++) {
        int row = wm * 64 + mt * 16 + (lane & 7) + ((q & 1) << 3);
        aBase[mt] = A_u + row * 256;
        aRx[mt]   = row & 7;
    }
    uint32_t bOff[2]; int bRx[2];
#pragma unroll
    for (int bt = 0; bt < 2; bt++) {
        int row = wn * 32 + bt * 16 + (lane & 7) + ((q & 1) << 3);
        bOff[bt] = row * 256;
        bRx[bt]  = row & 7;
    }

    float mrow[8], prow[8];
#pragma unroll
    for (int ri = 0; ri < 8; ri++) { mrow[ri] = -INFINITY; prow[ri] = 0.0f; }

    CP_WAIT0();
    __syncthreads();

    for (int t = 0; t < NTILES; t++) {
        // prefetch next B tile into the other buffer
        if (t + 1 < NTILES) {
            uint32_t bu = B_u + ((t + 1) & 1) * 32768;
            int jn = j0 + (t + 1) * TN;
#pragma unroll
            for (int v = 0; v < 8; v++) {
                int idx = tid + v * NTHREADS;
                int row = idx >> 4, c16 = idx & 15;
                CP_ASYNC16(bu + row * 256 + ((c16 ^ (row & 7)) << 4),
                           &g_featB[(size_t)(jn + row) * KD + c16 * 8]);
            }
            CP_COMMIT();
        }

        uint32_t bu = B_u + (t & 1) * 32768;
        float acc[4][4][4];
#pragma unroll
        for (int a = 0; a < 4; a++)
#pragma unroll
            for (int b = 0; b < 4; b++)
#pragma unroll
                for (int c = 0; c < 4; c++) acc[a][b][c] = 0.0f;

#pragma unroll
        for (int ks = 0; ks < 8; ks++) {
            uint32_t b0[4], b1[4];
            LDSM_X4(b0[0], b0[1], b0[2], b0[3],
                    bu + bOff[0] + (((ks * 2 + kh) ^ bRx[0]) << 4));
            LDSM_X4(b1[0], b1[1], b1[2], b1[3],
                    bu + bOff[1] + (((ks * 2 + kh) ^ bRx[1]) << 4));
#pragma unroll
            for (int mt = 0; mt < 4; mt++) {
                uint32_t a0, a1, a2, a3;
                LDSM_X4(a0, a1, a2, a3,
                        aBase[mt] + (((ks * 2 + kh) ^ aRx[mt]) << 4));
                MMA16816(acc[mt][0], a0, a1, a2, a3, b0[0], b0[2]);  // cols +0..7
                MMA16816(acc[mt][1], a0, a1, a2, a3, b0[1], b0[3]);  // cols +8..15
                MMA16816(acc[mt][2], a0, a1, a2, a3, b1[0], b1[2]);  // cols +16..23
                MMA16816(acc[mt][3], a0, a1, a2, a3, b1[1], b1[3]);  // cols +24..31
            }
        }

        // ---- epilogue: per-thread online softmax over own 8 cols x 8 rows ----
#pragma unroll
        for (int mt = 0; mt < 4; mt++) {
#pragma unroll
            for (int hh = 0; hh < 2; hh++) {
                int ri = mt * 2 + hh;
                float tmax = acc[mt][0][hh * 2];
                tmax = fmaxf(tmax, acc[mt][0][hh * 2 + 1]);
#pragma unroll
                for (int nt = 1; nt < 4; nt++) {
                    tmax = fmaxf(tmax, acc[mt][nt][hh * 2]);
                    tmax = fmaxf(tmax, acc[mt][nt][hh * 2 + 1]);
                }
                if (tmax > mrow[ri] - THRESH) {      // slow path (rare)
                    float newm = fmaxf(mrow[ri], tmax);
                    prow[ri] *= __expf(mrow[ri] - newm);
                    int ml = myLbl[ri];
#pragma unroll
                    for (int nt = 0; nt < 4; nt++) {
#pragma unroll
                        for (int e = 0; e < 2; e++) {
                            float v = acc[mt][nt][hh * 2 + e];
                            if (v > newm - THRESH) {
                                int col = t * TN + wn * 32 + nt * 8 + (lane & 3) * 2 + e;
                                if (sLbl[col] != ml) prow[ri] += __expf(v - newm);
                            }
                        }
                    }
                    mrow[ri] = newm;
                }
            }
        }

        CP_WAIT0();
        __syncthreads();
    }

    // ---- combine: quad lanes share rows ----
#pragma unroll
    for (int mt = 0; mt < 4; mt++) {
#pragma unroll
        for (int hh = 0; hh < 2; hh++) {
            int ri = mt * 2 + hh;
            float m_ = mrow[ri], p_ = prow[ri];
#pragma unroll
            for (int off = 1; off <= 2; off <<= 1) {
                float om = __shfl_xor_sync(0xffffffffu, m_, off);
                float op = __shfl_xor_sync(0xffffffffu, p_, off);
                float M = fmaxf(m_, om);
                p_ = p_ * expf(m_ - M) + op * expf(om - M);
                m_ = M;
            }
            if ((lane & 3) == 0) {
                int rowloc = wm * 64 + mt * 16 + hh * 8 + (lane >> 2);
                s_red[rowloc][wn] = make_float2(m_, p_);
            }
        }
    }
    __syncthreads();
    if (tid < 128) {
        float2 q0 = s_red[tid][0], q1 = s_red[tid][1];
        float2 q2 = s_red[tid][2], q3 = s_red[tid][3];
        float M = fmaxf(fmaxf(q0.x, q1.x), fmaxf(q2.x, q3.x));
        float P = q0.y * expf(q0.x - M) + q1.y * expf(q1.x - M)
                + q2.y * expf(q2.x - M) + q3.y * expf(q3.x - M);
        g_pm[(size_t)h * MD + i0 + tid] = make_float2(M, P);
    }
}

// ---------------------------------------------------------------- finalize
__global__ void k_final(const int* __restrict__ labels,
                        const float* __restrict__ ious,
                        float* __restrict__ out) {
    __shared__ float ssum[256], scnt[256];
    int tid = threadIdx.x;
    float sum = 0.0f, cnt = 0.0f;
    for (int i = tid; i < MD; i += 256) {
        if (ious[i] >= 0.5f) {
            float2 a = g_pm[i], b = g_pm[MD + i];
            float M = fmaxf(a.x, b.x);
            float ns = a.y * expf(a.x - M) + b.y * expf(b.x - M);
            int l = labels[i];
            l = l < 0 ? 0 : (l >= NCLS ? NCLS - 1 : l);
            float pc = (float)(g_hist[l] - 1);
            sum += ns / pc;
            cnt += 1.0f;
        }
    }
    ssum[tid] = sum; scnt[tid] = cnt;
    __syncthreads();
    for (int s = 128; s > 0; s >>= 1) {
        if (tid < s) { ssum[tid] += ssum[tid + s]; scnt[tid] += scnt[tid + s]; }
        __syncthreads();
    }
    if (tid == 0) out[0] = ssum[0] / scnt[0];
}

// ---------------------------------------------------------------- launch
extern "C" void kernel_launch(void* const* d_in, const int* in_sizes, int n_in,
                              void* d_out, int out_size) {
    const float* feat   = (const float*)d_in[0];
    const int*   labels = (const int*)  d_in[1];
    const float* ious   = (const float*)d_in[2];
    float*       out    = (float*)d_out;
    (void)in_sizes; (void)n_in; (void)out_size;

    const int smem_bytes = 32768 * 3 + 16384;   // A + 2xB + labels = 112KB
    cudaFuncSetAttribute(k_tensor, cudaFuncAttributeMaxDynamicSharedMemorySize, smem_bytes);

    k_convert<<<MD * KD / (256 * 8), 256>>>(feat);
    k_hist_zero<<<1, 32>>>();
    k_hist<<<MD / 256, 256>>>(labels);
    k_tensor<<<(MD / 128) * 2, NTHREADS, smem_bytes>>>(labels);
    k_final<<<1, 256>>>(labels, ious, out);
}

// round 4
// speedup vs baseline: 3.3651x; 1.3493x over previous
#include <cuda_runtime.h>
#include <cuda_bf16.h>
#include <math.h>
#include <stdint.h>

// ============================================================================
// GraphCut loss. bf16 mma.sync GEMM (HMMA), fused exact fp32 online softmax.
// R4: 512 threads (16 warps, warp tile 32x32), A fragments held in registers
// across the whole B-tile loop (A is loop-invariant; halves LDSM traffic).
// Features pre-scaled by sqrt(5). exp(x)==0 exactly for x<=-105 => fast path
// skips only provably-zero terms; all partial combines are exact LSE merges.
// ============================================================================

#define MD 8192
#define KD 128
#define NCLS 20
#define TN 128
#define NHALF 4096
#define NTILES (NHALF / TN)     // 32
#define NTHREADS 512
#define THRESH 105.0f

__device__ __align__(16) __nv_bfloat16 g_featB[(size_t)MD * KD];  // 2MB, *sqrt(5)
__device__ float2 g_pm[2 * MD];
__device__ int    g_hist[NCLS];

// ---------------------------------------------------------------- helpers
__device__ __forceinline__ uint32_t smem_u32(const void* p) {
    uint32_t a;
    asm("{ .reg .u64 t; cvta.to.shared.u64 t, %1; cvt.u32.u64 %0, t; }" : "=r"(a) : "l"(p));
    return a;
}
#define CP_ASYNC16(dst, src) \
    asm volatile("cp.async.cg.shared.global [%0], [%1], 16;" :: "r"(dst), "l"(src) : "memory")
#define CP_COMMIT() asm volatile("cp.async.commit_group;" ::: "memory")
#define CP_WAIT0()  asm volatile("cp.async.wait_group 0;" ::: "memory")
#define LDSM_X4(r0, r1, r2, r3, a) \
    asm volatile("ldmatrix.sync.aligned.m8n8.x4.shared.b16 {%0,%1,%2,%3}, [%4];" \
                 : "=r"(r0), "=r"(r1), "=r"(r2), "=r"(r3) : "r"(a))
#define MMA16816(c, a0, a1, a2, a3, b0, b1) \
    asm volatile("mma.sync.aligned.m16n8k16.row.col.f32.bf16.bf16.f32 " \
                 "{%0,%1,%2,%3},{%4,%5,%6,%7},{%8,%9},{%0,%1,%2,%3};" \
                 : "+f"((c)[0]), "+f"((c)[1]), "+f"((c)[2]), "+f"((c)[3]) \
                 : "r"(a0), "r"(a1), "r"(a2), "r"(a3), "r"(b0), "r"(b1))

// ---------------------------------------------------------------- convert
__global__ void k_convert(const float* __restrict__ feat) {
    const float SC = 2.23606797749979f;   // sqrt(1/0.2)
    int i = (blockIdx.x * 256 + threadIdx.x) * 8;
    float4 f0 = *(const float4*)&feat[i];
    float4 f1 = *(const float4*)&feat[i + 4];
    union { __nv_bfloat16 h[8]; uint4 u; } U;
    U.h[0] = __float2bfloat16(f0.x * SC); U.h[1] = __float2bfloat16(f0.y * SC);
    U.h[2] = __float2bfloat16(f0.z * SC); U.h[3] = __float2bfloat16(f0.w * SC);
    U.h[4] = __float2bfloat16(f1.x * SC); U.h[5] = __float2bfloat16(f1.y * SC);
    U.h[6] = __float2bfloat16(f1.z * SC); U.h[7] = __float2bfloat16(f1.w * SC);
    *(uint4*)&g_featB[i] = U.u;
}

// ---------------------------------------------------------------- histogram
__global__ void k_hist_zero() { if (threadIdx.x < NCLS) g_hist[threadIdx.x] = 0; }
__global__ void k_hist(const int* __restrict__ labels) {
    int i = blockIdx.x * blockDim.x + threadIdx.x;
    if (i < MD) {
        int l = labels[i];
        l = l < 0 ? 0 : (l >= NCLS ? NCLS - 1 : l);
        atomicAdd(&g_hist[l], 1);
    }
}

// ---------------------------------------------------------------- main kernel
// smem tile: 128 rows x 256B; 16B granule (row,c16) at row*256+((c16^(row&7))<<4)
__global__ void __launch_bounds__(NTHREADS, 1)
k_tensor(const int* __restrict__ labels) {
    extern __shared__ char dsm[];
    __shared__ float2 s_red[128][4];

    char* A_s  = dsm;                    // 32KB
    char* B_s  = dsm + 32768;            // 2 x 32KB
    int*  sLbl = (int*)(dsm + 98304);    // 16KB
    uint32_t A_u = smem_u32(A_s);
    uint32_t B_u = smem_u32(B_s);

    int tid  = threadIdx.x;
    int lane = tid & 31;
    int wid  = tid >> 5;
    int wm   = wid >> 2;                 // 0..3 : 32-row block
    int wn   = wid & 3;                  // 0..3 : 32-col block
    int r    = blockIdx.x >> 1;
    int h    = blockIdx.x & 1;
    int i0   = r * 128;
    int j0   = h * NHALF;

    // ---- prologue fills ----
#pragma unroll
    for (int v = 0; v < 4; v++) {
        int idx = tid + v * NTHREADS;          // 0..2047
        int row = idx >> 4, c16 = idx & 15;
        uint4 val = *(const uint4*)&g_featB[(size_t)(i0 + row) * KD + c16 * 8];
        *(uint4*)(A_s + row * 256 + ((c16 ^ (row & 7)) << 4)) = val;
    }
#pragma unroll
    for (int v = 0; v < 4; v++) {
        int idx = tid + v * NTHREADS;
        int row = idx >> 4, c16 = idx & 15;
        CP_ASYNC16(B_u + row * 256 + ((c16 ^ (row & 7)) << 4),
                   &g_featB[(size_t)(j0 + row) * KD + c16 * 8]);
    }
    CP_COMMIT();
#pragma unroll
    for (int v = tid; v < NHALF / 4; v += NTHREADS)
        ((int4*)sLbl)[v] = ((const int4*)(labels + j0))[v];

    int myLbl[4];
#pragma unroll
    for (int mt = 0; mt < 2; mt++)
#pragma unroll
        for (int hh = 0; hh < 2; hh++)
            myLbl[mt * 2 + hh] = labels[i0 + wm * 32 + mt * 16 + hh * 8 + (lane >> 2)];

    int q  = lane >> 3;                  // ldmatrix matrix id
    int kh = q >> 1;
    uint32_t aAddr[2]; int aRx[2];
#pragma unroll
    for (int mt = 0; mt < 2; mt++) {
        int row = wm * 32 + mt * 16 + (lane & 7) + ((q & 1) << 3);
        aAddr[mt] = A_u + row * 256;
        aRx[mt]   = row & 7;
    }
    uint32_t bOff[2]; int bRx[2];
#pragma unroll
    for (int bt = 0; bt < 2; bt++) {
        int row = wn * 32 + bt * 16 + (lane & 7) + ((q & 1) << 3);
        bOff[bt] = row * 256;
        bRx[bt]  = row & 7;
    }

    float mrow[4], prow[4];
#pragma unroll
    for (int ri = 0; ri < 4; ri++) { mrow[ri] = -INFINITY; prow[ri] = 0.0f; }

    __syncthreads();   // A_s visible

    // ---- load all A fragments once (loop-invariant) ----
    uint32_t aF[2][8][4];
#pragma unroll
    for (int mt = 0; mt < 2; mt++)
#pragma unroll
        for (int ks = 0; ks < 8; ks++)
            LDSM_X4(aF[mt][ks][0], aF[mt][ks][1], aF[mt][ks][2], aF[mt][ks][3],
                    aAddr[mt] + (((ks * 2 + kh) ^ aRx[mt]) << 4));

    CP_WAIT0();
    __syncthreads();   // B0 ready

    for (int t = 0; t < NTILES; t++) {
        if (t + 1 < NTILES) {
            uint32_t bu = B_u + ((t + 1) & 1) * 32768;
            int jn = j0 + (t + 1) * TN;
#pragma unroll
            for (int v = 0; v < 4; v++) {
                int idx = tid + v * NTHREADS;
                int row = idx >> 4, c16 = idx & 15;
                CP_ASYNC16(bu + row * 256 + ((c16 ^ (row & 7)) << 4),
                           &g_featB[(size_t)(jn + row) * KD + c16 * 8]);
            }
            CP_COMMIT();
        }

        uint32_t bu = B_u + (t & 1) * 32768;
        float acc[2][4][4];
#pragma unroll
        for (int a = 0; a < 2; a++)
#pragma unroll
            for (int b = 0; b < 4; b++)
#pragma unroll
                for (int c = 0; c < 4; c++) acc[a][b][c] = 0.0f;

#pragma unroll
        for (int ks = 0; ks < 8; ks++) {
            uint32_t b0[4], b1[4];
            LDSM_X4(b0[0], b0[1], b0[2], b0[3],
                    bu + bOff[0] + (((ks * 2 + kh) ^ bRx[0]) << 4));
            LDSM_X4(b1[0], b1[1], b1[2], b1[3],
                    bu + bOff[1] + (((ks * 2 + kh) ^ bRx[1]) << 4));
#pragma unroll
            for (int mt = 0; mt < 2; mt++) {
                MMA16816(acc[mt][0], aF[mt][ks][0], aF[mt][ks][1], aF[mt][ks][2], aF[mt][ks][3], b0[0], b0[2]);
                MMA16816(acc[mt][1], aF[mt][ks][0], aF[mt][ks][1], aF[mt][ks][2], aF[mt][ks][3], b0[1], b0[3]);
                MMA16816(acc[mt][2], aF[mt][ks][0], aF[mt][ks][1], aF[mt][ks][2], aF[mt][ks][3], b1[0], b1[2]);
                MMA16816(acc[mt][3], aF[mt][ks][0], aF[mt][ks][1], aF[mt][ks][2], aF[mt][ks][3], b1[1], b1[3]);
            }
        }

        // ---- epilogue: per-thread online softmax (8 cols x 4 rows) ----
#pragma unroll
        for (int mt = 0; mt < 2; mt++) {
#pragma unroll
            for (int hh = 0; hh < 2; hh++) {
                int ri = mt * 2 + hh;
                float tmax = acc[mt][0][hh * 2];
                tmax = fmaxf(tmax, acc[mt][0][hh * 2 + 1]);
#pragma unroll
                for (int nt = 1; nt < 4; nt++) {
                    tmax = fmaxf(tmax, acc[mt][nt][hh * 2]);
                    tmax = fmaxf(tmax, acc[mt][nt][hh * 2 + 1]);
                }
                if (tmax > mrow[ri] - THRESH) {      // rare slow path
                    float newm = fmaxf(mrow[ri], tmax);
                    prow[ri] *= __expf(mrow[ri] - newm);
                    int ml = myLbl[ri];
#pragma unroll
                    for (int nt = 0; nt < 4; nt++) {
#pragma unroll
                        for (int e = 0; e < 2; e++) {
                            float v = acc[mt][nt][hh * 2 + e];
                            if (v > newm - THRESH) {
                                int col = t * TN + wn * 32 + nt * 8 + (lane & 3) * 2 + e;
                                if (sLbl[col] != ml) prow[ri] += __expf(v - newm);
                            }
                        }
                    }
                    mrow[ri] = newm;
                }
            }
        }

        CP_WAIT0();
        __syncthreads();
    }

    // ---- combine partials ----
#pragma unroll
    for (int mt = 0; mt < 2; mt++) {
#pragma unroll
        for (int hh = 0; hh < 2; hh++) {
            int ri = mt * 2 + hh;
            float m_ = mrow[ri], p_ = prow[ri];
#pragma unroll
            for (int off = 1; off <= 2; off <<= 1) {
                float om = __shfl_xor_sync(0xffffffffu, m_, off);
                float op = __shfl_xor_sync(0xffffffffu, p_, off);
                float M = fmaxf(m_, om);
                p_ = p_ * expf(m_ - M) + op * expf(om - M);
                m_ = M;
            }
            if ((lane & 3) == 0) {
                int rowloc = wm * 32 + mt * 16 + hh * 8 + (lane >> 2);
                s_red[rowloc][wn] = make_float2(m_, p_);
            }
        }
    }
    __syncthreads();
    if (tid < 128) {
        float2 q0 = s_red[tid][0], q1 = s_red[tid][1];
        float2 q2 = s_red[tid][2], q3 = s_red[tid][3];
        float M = fmaxf(fmaxf(q0.x, q1.x), fmaxf(q2.x, q3.x));
        float P = q0.y * expf(q0.x - M) + q1.y * expf(q1.x - M)
                + q2.y * expf(q2.x - M) + q3.y * expf(q3.x - M);
        g_pm[(size_t)h * MD + i0 + tid] = make_float2(M, P);
    }
}

// ---------------------------------------------------------------- finalize
__global__ void k_final(const int* __restrict__ labels,
                        const float* __restrict__ ious,
                        float* __restrict__ out) {
    __shared__ float ssum[256], scnt[256];
    int tid = threadIdx.x;
    float sum = 0.0f, cnt = 0.0f;
    for (int i = tid; i < MD; i += 256) {
        if (ious[i] >= 0.5f) {
            float2 a = g_pm[i], b = g_pm[MD + i];
            float M = fmaxf(a.x, b.x);
            float ns = a.y * expf(a.x - M) + b.y * expf(b.x - M);
            int l = labels[i];
            l = l < 0 ? 0 : (l >= NCLS ? NCLS - 1 : l);
            float pc = (float)(g_hist[l] - 1);
            sum += ns / pc;
            cnt += 1.0f;
        }
    }
    ssum[tid] = sum; scnt[tid] = cnt;
    __syncthreads();
    for (int s = 128; s > 0; s >>= 1) {
        if (tid < s) { ssum[tid] += ssum[tid + s]; scnt[tid] += scnt[tid + s]; }
        __syncthreads();
    }
    if (tid == 0) out[0] = ssum[0] / scnt[0];
}

// ---------------------------------------------------------------- launch
extern "C" void kernel_launch(void* const* d_in, const int* in_sizes, int n_in,
                              void* d_out, int out_size) {
    const float* feat   = (const float*)d_in[0];
    const int*   labels = (const int*)  d_in[1];
    const float* ious   = (const float*)d_in[2];
    float*       out    = (float*)d_out;
    (void)in_sizes; (void)n_in; (void)out_size;

    const int smem_bytes = 32768 * 3 + 16384;   // A + 2xB + labels = 112KB
    cudaFuncSetAttribute(k_tensor, cudaFuncAttributeMaxDynamicSharedMemorySize, smem_bytes);

    k_convert<<<MD * KD / (256 * 8), 256>>>(feat);
    k_hist_zero<<<1, 32>>>();
    k_hist<<<MD / 256, 256>>>(labels);
    k_tensor<<<(MD / 128) * 2, NTHREADS, smem_bytes>>>(labels);
    k_final<<<1, 256>>>(labels, ious, out);
}

// round 5
// speedup vs baseline: 4.3471x; 1.2918x over previous
#include <cuda_runtime.h>
#include <cuda_bf16.h>
#include <math.h>
#include <stdint.h>

// ============================================================================
// GraphCut loss. bf16 mma.sync GEMM (HMMA), fused exact fp32 online softmax.
// R5: 256 CTAs (64 row-blocks x 4 col quarters), 2 CTAs/SM (occ 50%), 64 regs,
// A re-ldmatrix'ed per tile, int8 labels in smem, hist folded into k_final.
// Features pre-scaled by sqrt(5). exp(x)==0 exactly for x<=-105 => fast path
// skips only provably-zero terms; all partial combines are exact LSE merges.
// ============================================================================

#define MD 8192
#define KD 128
#define NCLS 20
#define TN 128
#define NQ 2048
#define NTILES (NQ / TN)        // 16
#define NTHREADS 512
#define THRESH 105.0f

__device__ __align__(16) __nv_bfloat16 g_featB[(size_t)MD * KD];  // 2MB, *sqrt(5)
__device__ float2 g_pm[4 * MD];   // per-quarter (rowmax, partial neg_sum)

// ---------------------------------------------------------------- helpers
__device__ __forceinline__ uint32_t smem_u32(const void* p) {
    uint32_t a;
    asm("{ .reg .u64 t; cvta.to.shared.u64 t, %1; cvt.u32.u64 %0, t; }" : "=r"(a) : "l"(p));
    return a;
}
#define CP_ASYNC16(dst, src) \
    asm volatile("cp.async.cg.shared.global [%0], [%1], 16;" :: "r"(dst), "l"(src) : "memory")
#define CP_COMMIT() asm volatile("cp.async.commit_group;" ::: "memory")
#define CP_WAIT0()  asm volatile("cp.async.wait_group 0;" ::: "memory")
#define LDSM_X4(r0, r1, r2, r3, a) \
    asm volatile("ldmatrix.sync.aligned.m8n8.x4.shared.b16 {%0,%1,%2,%3}, [%4];" \
                 : "=r"(r0), "=r"(r1), "=r"(r2), "=r"(r3) : "r"(a))
#define MMA16816(c, a0, a1, a2, a3, b0, b1) \
    asm volatile("mma.sync.aligned.m16n8k16.row.col.f32.bf16.bf16.f32 " \
                 "{%0,%1,%2,%3},{%4,%5,%6,%7},{%8,%9},{%0,%1,%2,%3};" \
                 : "+f"((c)[0]), "+f"((c)[1]), "+f"((c)[2]), "+f"((c)[3]) \
                 : "r"(a0), "r"(a1), "r"(a2), "r"(a3), "r"(b0), "r"(b1))

// ---------------------------------------------------------------- convert
__global__ void k_convert(const float* __restrict__ feat) {
    const float SC = 2.23606797749979f;   // sqrt(1/0.2)
    int i = (blockIdx.x * 256 + threadIdx.x) * 8;
    float4 f0 = *(const float4*)&feat[i];
    float4 f1 = *(const float4*)&feat[i + 4];
    union { __nv_bfloat16 h[8]; uint4 u; } U;
    U.h[0] = __float2bfloat16(f0.x * SC); U.h[1] = __float2bfloat16(f0.y * SC);
    U.h[2] = __float2bfloat16(f0.z * SC); U.h[3] = __float2bfloat16(f0.w * SC);
    U.h[4] = __float2bfloat16(f1.x * SC); U.h[5] = __float2bfloat16(f1.y * SC);
    U.h[6] = __float2bfloat16(f1.z * SC); U.h[7] = __float2bfloat16(f1.w * SC);
    *(uint4*)&g_featB[i] = U.u;
}

// ---------------------------------------------------------------- main kernel
// smem tile: 128 rows x 256B; 16B granule (row,c16) at row*256+((c16^(row&7))<<4)
__global__ void __launch_bounds__(NTHREADS, 2)
k_tensor(const int* __restrict__ labels) {
    extern __shared__ char dsm[];
    __shared__ float2 s_red[128][4];

    char* A_s  = dsm;                        // 32KB
    char* B_s  = dsm + 32768;                // 2 x 32KB
    unsigned char* sLbl = (unsigned char*)(dsm + 98304);   // 2KB (int8 labels)
    uint32_t A_u = smem_u32(A_s);
    uint32_t B_u = smem_u32(B_s);

    int tid  = threadIdx.x;
    int lane = tid & 31;
    int wid  = tid >> 5;
    int wm   = wid >> 2;                 // 0..3 : 32-row block
    int wn   = wid & 3;                  // 0..3 : 32-col block
    int r    = blockIdx.x >> 2;
    int qd   = blockIdx.x & 3;
    int i0   = r * 128;
    int j0   = qd * NQ;

    // ---- prologue fills ----
#pragma unroll
    for (int v = 0; v < 4; v++) {
        int idx = tid + v * NTHREADS;          // 0..2047
        int row = idx >> 4, c16 = idx & 15;
        uint4 val = *(const uint4*)&g_featB[(size_t)(i0 + row) * KD + c16 * 8];
        *(uint4*)(A_s + row * 256 + ((c16 ^ (row & 7)) << 4)) = val;
    }
#pragma unroll
    for (int v = 0; v < 4; v++) {
        int idx = tid + v * NTHREADS;
        int row = idx >> 4, c16 = idx & 15;
        CP_ASYNC16(B_u + row * 256 + ((c16 ^ (row & 7)) << 4),
                   &g_featB[(size_t)(j0 + row) * KD + c16 * 8]);
    }
    CP_COMMIT();
    {   // labels -> int8 smem (one int4 = 4 labels per thread)
        int v = tid;                            // 512 threads x 4 = 2048
        int4 L = ((const int4*)(labels + j0))[v];
        ((uint32_t*)sLbl)[v] = (uint32_t)(L.x & 255) | ((uint32_t)(L.y & 255) << 8)
                             | ((uint32_t)(L.z & 255) << 16) | ((uint32_t)(L.w & 255) << 24);
    }

    int myLbl[4];
#pragma unroll
    for (int mt = 0; mt < 2; mt++)
#pragma unroll
        for (int hh = 0; hh < 2; hh++)
            myLbl[mt * 2 + hh] = labels[i0 + wm * 32 + mt * 16 + hh * 8 + (lane >> 2)];

    int q  = lane >> 3;                  // ldmatrix matrix id
    int kh = q >> 1;
    uint32_t aAddr[2]; int aRx[2];
#pragma unroll
    for (int mt = 0; mt < 2; mt++) {
        int row = wm * 32 + mt * 16 + (lane & 7) + ((q & 1) << 3);
        aAddr[mt] = A_u + row * 256;
        aRx[mt]   = row & 7;
    }
    uint32_t bOff[2]; int bRx[2];
#pragma unroll
    for (int bt = 0; bt < 2; bt++) {
        int row = wn * 32 + bt * 16 + (lane & 7) + ((q & 1) << 3);
        bOff[bt] = row * 256;
        bRx[bt]  = row & 7;
    }

    float mrow[4], prow[4];
#pragma unroll
    for (int ri = 0; ri < 4; ri++) { mrow[ri] = -INFINITY; prow[ri] = 0.0f; }

    CP_WAIT0();
    __syncthreads();   // A_s + B0 + labels ready

    for (int t = 0; t < NTILES; t++) {
        if (t + 1 < NTILES) {
            uint32_t bu = B_u + ((t + 1) & 1) * 32768;
            int jn = j0 + (t + 1) * TN;
#pragma unroll
            for (int v = 0; v < 4; v++) {
                int idx = tid + v * NTHREADS;
                int row = idx >> 4, c16 = idx & 15;
                CP_ASYNC16(bu + row * 256 + ((c16 ^ (row & 7)) << 4),
                           &g_featB[(size_t)(jn + row) * KD + c16 * 8]);
            }
            CP_COMMIT();
        }

        uint32_t bu = B_u + (t & 1) * 32768;
        float acc[2][4][4];
#pragma unroll
        for (int a = 0; a < 2; a++)
#pragma unroll
            for (int b = 0; b < 4; b++)
#pragma unroll
                for (int c = 0; c < 4; c++) acc[a][b][c] = 0.0f;

#pragma unroll
        for (int ks = 0; ks < 8; ks++) {
            uint32_t b0[4], b1[4], a0[4], a1[4];
            LDSM_X4(b0[0], b0[1], b0[2], b0[3],
                    bu + bOff[0] + (((ks * 2 + kh) ^ bRx[0]) << 4));
            LDSM_X4(b1[0], b1[1], b1[2], b1[3],
                    bu + bOff[1] + (((ks * 2 + kh) ^ bRx[1]) << 4));
            LDSM_X4(a0[0], a0[1], a0[2], a0[3],
                    aAddr[0] + (((ks * 2 + kh) ^ aRx[0]) << 4));
            LDSM_X4(a1[0], a1[1], a1[2], a1[3],
                    aAddr[1] + (((ks * 2 + kh) ^ aRx[1]) << 4));
            MMA16816(acc[0][0], a0[0], a0[1], a0[2], a0[3], b0[0], b0[2]);
            MMA16816(acc[0][1], a0[0], a0[1], a0[2], a0[3], b0[1], b0[3]);
            MMA16816(acc[0][2], a0[0], a0[1], a0[2], a0[3], b1[0], b1[2]);
            MMA16816(acc[0][3], a0[0], a0[1], a0[2], a0[3], b1[1], b1[3]);
            MMA16816(acc[1][0], a1[0], a1[1], a1[2], a1[3], b0[0], b0[2]);
            MMA16816(acc[1][1], a1[0], a1[1], a1[2], a1[3], b0[1], b0[3]);
            MMA16816(acc[1][2], a1[0], a1[1], a1[2], a1[3], b1[0], b1[2]);
            MMA16816(acc[1][3], a1[0], a1[1], a1[2], a1[3], b1[1], b1[3]);
        }

        // ---- epilogue: per-thread online softmax (8 cols x 4 rows) ----
#pragma unroll
        for (int mt = 0; mt < 2; mt++) {
#pragma unroll
            for (int hh = 0; hh < 2; hh++) {
                int ri = mt * 2 + hh;
                float tmax = acc[mt][0][hh * 2];
                tmax = fmaxf(tmax, acc[mt][0][hh * 2 + 1]);
#pragma unroll
                for (int nt = 1; nt < 4; nt++) {
                    tmax = fmaxf(tmax, acc[mt][nt][hh * 2]);
                    tmax = fmaxf(tmax, acc[mt][nt][hh * 2 + 1]);
                }
                if (tmax > mrow[ri] - THRESH) {      // rare slow path
                    float newm = fmaxf(mrow[ri], tmax);
                    prow[ri] *= __expf(mrow[ri] - newm);
                    int ml = myLbl[ri];
#pragma unroll
                    for (int nt = 0; nt < 4; nt++) {
#pragma unroll
                        for (int e = 0; e < 2; e++) {
                            float v = acc[mt][nt][hh * 2 + e];
                            if (v > newm - THRESH) {
                                int col = t * TN + wn * 32 + nt * 8 + (lane & 3) * 2 + e;
                                if ((int)sLbl[col] != ml) prow[ri] += __expf(v - newm);
                            }
                        }
                    }
                    mrow[ri] = newm;
                }
            }
        }

        CP_WAIT0();
        __syncthreads();
    }

    // ---- combine partials ----
#pragma unroll
    for (int mt = 0; mt < 2; mt++) {
#pragma unroll
        for (int hh = 0; hh < 2; hh++) {
            int ri = mt * 2 + hh;
            float m_ = mrow[ri], p_ = prow[ri];
#pragma unroll
            for (int off = 1; off <= 2; off <<= 1) {
                float om = __shfl_xor_sync(0xffffffffu, m_, off);
                float op = __shfl_xor_sync(0xffffffffu, p_, off);
                float M = fmaxf(m_, om);
                p_ = p_ * expf(m_ - M) + op * expf(om - M);
                m_ = M;
            }
            if ((lane & 3) == 0) {
                int rowloc = wm * 32 + mt * 16 + hh * 8 + (lane >> 2);
                s_red[rowloc][wn] = make_float2(m_, p_);
            }
        }
    }
    __syncthreads();
    if (tid < 128) {
        float2 q0 = s_red[tid][0], q1 = s_red[tid][1];
        float2 q2 = s_red[tid][2], q3 = s_red[tid][3];
        float M = fmaxf(fmaxf(q0.x, q1.x), fmaxf(q2.x, q3.x));
        float P = q0.y * expf(q0.x - M) + q1.y * expf(q1.x - M)
                + q2.y * expf(q2.x - M) + q3.y * expf(q3.x - M);
        g_pm[(size_t)qd * MD + i0 + tid] = make_float2(M, P);
    }
}

// ---------------------------------------------------------------- finalize
__global__ void k_final(const int* __restrict__ labels,
                        const float* __restrict__ ious,
                        float* __restrict__ out) {
    __shared__ float ssum[256], scnt[256];
    __shared__ int hist[NCLS];
    int tid = threadIdx.x;
    if (tid < NCLS) hist[tid] = 0;
    __syncthreads();
    for (int i = tid; i < MD; i += 256) {
        int l = labels[i];
        l = l < 0 ? 0 : (l >= NCLS ? NCLS - 1 : l);
        atomicAdd(&hist[l], 1);
    }
    __syncthreads();

    float sum = 0.0f, cnt = 0.0f;
    for (int i = tid; i < MD; i += 256) {
        if (ious[i] >= 0.5f) {
            float2 a = g_pm[i], b = g_pm[MD + i];
            float2 c = g_pm[2 * MD + i], d = g_pm[3 * MD + i];
            float M = fmaxf(fmaxf(a.x, b.x), fmaxf(c.x, d.x));
            float ns = a.y * expf(a.x - M) + b.y * expf(b.x - M)
                     + c.y * expf(c.x - M) + d.y * expf(d.x - M);
            int l = labels[i];
            l = l < 0 ? 0 : (l >= NCLS ? NCLS - 1 : l);
            float pc = (float)(hist[l] - 1);
            sum += ns / pc;
            cnt += 1.0f;
        }
    }
    ssum[tid] = sum; scnt[tid] = cnt;
    __syncthreads();
    for (int s = 128; s > 0; s >>= 1) {
        if (tid < s) { ssum[tid] += ssum[tid + s]; scnt[tid] += scnt[tid + s]; }
        __syncthreads();
    }
    if (tid == 0) out[0] = ssum[0] / scnt[0];
}

// ---------------------------------------------------------------- launch
extern "C" void kernel_launch(void* const* d_in, const int* in_sizes, int n_in,
                              void* d_out, int out_size) {
    const float* feat   = (const float*)d_in[0];
    const int*   labels = (const int*)  d_in[1];
    const float* ious   = (const float*)d_in[2];
    float*       out    = (float*)d_out;
    (void)in_sizes; (void)n_in; (void)out_size;

    const int smem_bytes = 98304 + 2048;   // A 32K + 2xB 64K + labels 2K
    cudaFuncSetAttribute(k_tensor, cudaFuncAttributeMaxDynamicSharedMemorySize, smem_bytes);

    k_convert<<<MD * KD / (256 * 8), 256>>>(feat);
    k_tensor<<<(MD / 128) * 4, NTHREADS, smem_bytes>>>(labels);
    k_final<<<1, 256>>>(labels, ious, out);
}

// round 6
// speedup vs baseline: 6.6996x; 1.5412x over previous
#include <cuda_runtime.h>
#include <cuda_bf16.h>
#include <math.h>
#include <stdint.h>

// ============================================================================
// GraphCut loss. bf16 mma.sync GEMM (HMMA), fused exact fp32 online softmax.
// R6: online-max seeded with the self-similarity term s_ii = |f_i*sqrt5|^2
// (diagonal belongs to the row, so this is an algebraic identity, not an
// approximation) => epilogue fast path (fmax+cmp only) on every tile; the
// exact guarded-exp slow path remains and fires whenever any value comes
// within 105 of the seed. exp(x)==0 exactly for x<=-105 in fp32, so every
// skipped term equals the reference's term exactly.
// 2 CTAs/SM (512 thr), 256 CTAs = 64 row-blocks x 4 col quarters.
// ============================================================================

#define MD 8192
#define KD 128
#define NCLS 20
#define TN 128
#define NQ 2048
#define NTILES (NQ / TN)        // 16
#define NTHREADS 512
#define THRESH 105.0f

__device__ __align__(16) __nv_bfloat16 g_featB[(size_t)MD * KD];  // 2MB, *sqrt(5)
__device__ float2 g_pm[4 * MD];   // per-quarter (rowmax, partial neg_sum)

// ---------------------------------------------------------------- helpers
__device__ __forceinline__ uint32_t smem_u32(const void* p) {
    uint32_t a;
    asm("{ .reg .u64 t; cvta.to.shared.u64 t, %1; cvt.u32.u64 %0, t; }" : "=r"(a) : "l"(p));
    return a;
}
#define CP_ASYNC16(dst, src) \
    asm volatile("cp.async.cg.shared.global [%0], [%1], 16;" :: "r"(dst), "l"(src) : "memory")
#define CP_COMMIT() asm volatile("cp.async.commit_group;" ::: "memory")
#define CP_WAIT0()  asm volatile("cp.async.wait_group 0;" ::: "memory")
#define LDSM_X4(r0, r1, r2, r3, a) \
    asm volatile("ldmatrix.sync.aligned.m8n8.x4.shared.b16 {%0,%1,%2,%3}, [%4];" \
                 : "=r"(r0), "=r"(r1), "=r"(r2), "=r"(r3) : "r"(a))
#define MMA16816(c, a0, a1, a2, a3, b0, b1) \
    asm volatile("mma.sync.aligned.m16n8k16.row.col.f32.bf16.bf16.f32 " \
                 "{%0,%1,%2,%3},{%4,%5,%6,%7},{%8,%9},{%0,%1,%2,%3};" \
                 : "+f"((c)[0]), "+f"((c)[1]), "+f"((c)[2]), "+f"((c)[3]) \
                 : "r"(a0), "r"(a1), "r"(a2), "r"(a3), "r"(b0), "r"(b1))

// ---------------------------------------------------------------- convert
__global__ void k_convert(const float* __restrict__ feat) {
    const float SC = 2.23606797749979f;   // sqrt(1/0.2)
    int i = (blockIdx.x * 256 + threadIdx.x) * 8;
    float4 f0 = *(const float4*)&feat[i];
    float4 f1 = *(const float4*)&feat[i + 4];
    union { __nv_bfloat16 h[8]; uint4 u; } U;
    U.h[0] = __float2bfloat16(f0.x * SC); U.h[1] = __float2bfloat16(f0.y * SC);
    U.h[2] = __float2bfloat16(f0.z * SC); U.h[3] = __float2bfloat16(f0.w * SC);
    U.h[4] = __float2bfloat16(f1.x * SC); U.h[5] = __float2bfloat16(f1.y * SC);
    U.h[6] = __float2bfloat16(f1.z * SC); U.h[7] = __float2bfloat16(f1.w * SC);
    *(uint4*)&g_featB[i] = U.u;
}

// ---------------------------------------------------------------- main kernel
// smem tile: 128 rows x 256B; 16B granule (row,c16) at row*256+((c16^(row&7))<<4)
__global__ void __launch_bounds__(NTHREADS, 2)
k_tensor(const int* __restrict__ labels) {
    extern __shared__ char dsm[];
    __shared__ float2 s_red[128][4];
    __shared__ float  s_seed[128];

    char* A_s  = dsm;                        // 32KB
    char* B_s  = dsm + 32768;                // 2 x 32KB
    unsigned char* sLbl = (unsigned char*)(dsm + 98304);   // 2KB (int8 labels)
    uint32_t A_u = smem_u32(A_s);
    uint32_t B_u = smem_u32(B_s);

    int tid  = threadIdx.x;
    int lane = tid & 31;
    int wid  = tid >> 5;
    int wm   = wid >> 2;                 // 0..3 : 32-row block
    int wn   = wid & 3;                  // 0..3 : 32-col block
    int r    = blockIdx.x >> 2;
    int qd   = blockIdx.x & 3;
    int i0   = r * 128;
    int j0   = qd * NQ;

    // ---- prologue fills ----
#pragma unroll
    for (int v = 0; v < 4; v++) {
        int idx = tid + v * NTHREADS;          // 0..2047
        int row = idx >> 4, c16 = idx & 15;
        uint4 val = *(const uint4*)&g_featB[(size_t)(i0 + row) * KD + c16 * 8];
        *(uint4*)(A_s + row * 256 + ((c16 ^ (row & 7)) << 4)) = val;
    }
#pragma unroll
    for (int v = 0; v < 4; v++) {
        int idx = tid + v * NTHREADS;
        int row = idx >> 4, c16 = idx & 15;
        CP_ASYNC16(B_u + row * 256 + ((c16 ^ (row & 7)) << 4),
                   &g_featB[(size_t)(j0 + row) * KD + c16 * 8]);
    }
    CP_COMMIT();
    {   // labels -> int8 smem
        int4 L = ((const int4*)(labels + j0))[tid];
        ((uint32_t*)sLbl)[tid] = (uint32_t)(L.x & 255) | ((uint32_t)(L.y & 255) << 8)
                               | ((uint32_t)(L.z & 255) << 16) | ((uint32_t)(L.w & 255) << 24);
    }
    {   // self-dot seeds: thread quad (sr, sq) sums 32 bf16^2 of row i0+sr
        int sr = tid >> 2, sq = tid & 3;
        const uint4* rp = (const uint4*)&g_featB[(size_t)(i0 + sr) * KD + sq * 32];
        float sacc = 0.0f;
#pragma unroll
        for (int g = 0; g < 4; g++) {
            uint4 u = rp[g];
            uint32_t w[4] = {u.x, u.y, u.z, u.w};
#pragma unroll
            for (int e = 0; e < 4; e++) {
                float lo = __uint_as_float(w[e] << 16);
                float hi = __uint_as_float(w[e] & 0xffff0000u);
                sacc = fmaf(lo, lo, sacc);
                sacc = fmaf(hi, hi, sacc);
            }
        }
        sacc += __shfl_xor_sync(0xffffffffu, sacc, 1);
        sacc += __shfl_xor_sync(0xffffffffu, sacc, 2);
        if (sq == 0) s_seed[sr] = sacc;
    }

    int myLbl[4];
#pragma unroll
    for (int mt = 0; mt < 2; mt++)
#pragma unroll
        for (int hh = 0; hh < 2; hh++)
            myLbl[mt * 2 + hh] = labels[i0 + wm * 32 + mt * 16 + hh * 8 + (lane >> 2)];

    int q  = lane >> 3;                  // ldmatrix matrix id
    int kh = q >> 1;
    uint32_t aAddr[2]; int aRx[2];
#pragma unroll
    for (int mt = 0; mt < 2; mt++) {
        int row = wm * 32 + mt * 16 + (lane & 7) + ((q & 1) << 3);
        aAddr[mt] = A_u + row * 256;
        aRx[mt]   = row & 7;
    }
    uint32_t bOff[2]; int bRx[2];
#pragma unroll
    for (int bt = 0; bt < 2; bt++) {
        int row = wn * 32 + bt * 16 + (lane & 7) + ((q & 1) << 3);
        bOff[bt] = row * 256;
        bRx[bt]  = row & 7;
    }

    CP_WAIT0();
    __syncthreads();   // A_s + B0 + labels + seeds ready

    // ---- seed online max with self-similarity (exact: diag is in the row) ----
    float mrow[4], prow[4];
#pragma unroll
    for (int mt = 0; mt < 2; mt++)
#pragma unroll
        for (int hh = 0; hh < 2; hh++) {
            mrow[mt * 2 + hh] = s_seed[wm * 32 + mt * 16 + hh * 8 + (lane >> 2)];
            prow[mt * 2 + hh] = 0.0f;
        }

    for (int t = 0; t < NTILES; t++) {
        if (t + 1 < NTILES) {
            uint32_t bu = B_u + ((t + 1) & 1) * 32768;
            int jn = j0 + (t + 1) * TN;
#pragma unroll
            for (int v = 0; v < 4; v++) {
                int idx = tid + v * NTHREADS;
                int row = idx >> 4, c16 = idx & 15;
                CP_ASYNC16(bu + row * 256 + ((c16 ^ (row & 7)) << 4),
                           &g_featB[(size_t)(jn + row) * KD + c16 * 8]);
            }
            CP_COMMIT();
        }

        uint32_t bu = B_u + (t & 1) * 32768;
        float acc[2][4][4];
#pragma unroll
        for (int a = 0; a < 2; a++)
#pragma unroll
            for (int b = 0; b < 4; b++)
#pragma unroll
                for (int c = 0; c < 4; c++) acc[a][b][c] = 0.0f;

#pragma unroll
        for (int ks = 0; ks < 8; ks++) {
            uint32_t b0[4], b1[4], a0[4], a1[4];
            LDSM_X4(b0[0], b0[1], b0[2], b0[3],
                    bu + bOff[0] + (((ks * 2 + kh) ^ bRx[0]) << 4));
            LDSM_X4(b1[0], b1[1], b1[2], b1[3],
                    bu + bOff[1] + (((ks * 2 + kh) ^ bRx[1]) << 4));
            LDSM_X4(a0[0], a0[1], a0[2], a0[3],
                    aAddr[0] + (((ks * 2 + kh) ^ aRx[0]) << 4));
            LDSM_X4(a1[0], a1[1], a1[2], a1[3],
                    aAddr[1] + (((ks * 2 + kh) ^ aRx[1]) << 4));
            MMA16816(acc[0][0], a0[0], a0[1], a0[2], a0[3], b0[0], b0[2]);
            MMA16816(acc[0][1], a0[0], a0[1], a0[2], a0[3], b0[1], b0[3]);
            MMA16816(acc[0][2], a0[0], a0[1], a0[2], a0[3], b1[0], b1[2]);
            MMA16816(acc[0][3], a0[0], a0[1], a0[2], a0[3], b1[1], b1[3]);
            MMA16816(acc[1][0], a1[0], a1[1], a1[2], a1[3], b0[0], b0[2]);
            MMA16816(acc[1][1], a1[0], a1[1], a1[2], a1[3], b0[1], b0[3]);
            MMA16816(acc[1][2], a1[0], a1[1], a1[2], a1[3], b1[0], b1[2]);
            MMA16816(acc[1][3], a1[0], a1[1], a1[2], a1[3], b1[1], b1[3]);
        }

        // ---- epilogue: fast path = fmax + single compare per row slot ----
#pragma unroll
        for (int mt = 0; mt < 2; mt++) {
#pragma unroll
            for (int hh = 0; hh < 2; hh++) {
                int ri = mt * 2 + hh;
                float tmax = acc[mt][0][hh * 2];
                tmax = fmaxf(tmax, acc[mt][0][hh * 2 + 1]);
#pragma unroll
                for (int nt = 1; nt < 4; nt++) {
                    tmax = fmaxf(tmax, acc[mt][nt][hh * 2]);
                    tmax = fmaxf(tmax, acc[mt][nt][hh * 2 + 1]);
                }
                if (__builtin_expect(tmax > mrow[ri] - THRESH, 0)) {  // cold
                    float newm = fmaxf(mrow[ri], tmax);
                    prow[ri] *= __expf(mrow[ri] - newm);
                    int ml = myLbl[ri];
#pragma unroll
                    for (int nt = 0; nt < 4; nt++) {
#pragma unroll
                        for (int e = 0; e < 2; e++) {
                            float v = acc[mt][nt][hh * 2 + e];
                            if (v > newm - THRESH) {
                                int col = t * TN + wn * 32 + nt * 8 + (lane & 3) * 2 + e;
                                if ((int)sLbl[col] != ml) prow[ri] += __expf(v - newm);
                            }
                        }
                    }
                    mrow[ri] = newm;
                }
            }
        }

        CP_WAIT0();
        __syncthreads();
    }

    // ---- combine partials ----
#pragma unroll
    for (int mt = 0; mt < 2; mt++) {
#pragma unroll
        for (int hh = 0; hh < 2; hh++) {
            int ri = mt * 2 + hh;
            float m_ = mrow[ri], p_ = prow[ri];
#pragma unroll
            for (int off = 1; off <= 2; off <<= 1) {
                float om = __shfl_xor_sync(0xffffffffu, m_, off);
                float op = __shfl_xor_sync(0xffffffffu, p_, off);
                float M = fmaxf(m_, om);
                p_ = p_ * expf(m_ - M) + op * expf(om - M);
                m_ = M;
            }
            if ((lane & 3) == 0) {
                int rowloc = wm * 32 + mt * 16 + hh * 8 + (lane >> 2);
                s_red[rowloc][wn] = make_float2(m_, p_);
            }
        }
    }
    __syncthreads();
    if (tid < 128) {
        float2 q0 = s_red[tid][0], q1 = s_red[tid][1];
        float2 q2 = s_red[tid][2], q3 = s_red[tid][3];
        float M = fmaxf(fmaxf(q0.x, q1.x), fmaxf(q2.x, q3.x));
        float P = q0.y * expf(q0.x - M) + q1.y * expf(q1.x - M)
                + q2.y * expf(q2.x - M) + q3.y * expf(q3.x - M);
        g_pm[(size_t)qd * MD + i0 + tid] = make_float2(M, P);
    }
}

// ---------------------------------------------------------------- finalize
__global__ void k_final(const int* __restrict__ labels,
                        const float* __restrict__ ious,
                        float* __restrict__ out) {
    __shared__ float ssum[256], scnt[256];
    __shared__ int hist[NCLS];
    int tid = threadIdx.x;
    if (tid < NCLS) hist[tid] = 0;
    __syncthreads();
    for (int i = tid; i < MD; i += 256) {
        int l = labels[i];
        l = l < 0 ? 0 : (l >= NCLS ? NCLS - 1 : l);
        atomicAdd(&hist[l], 1);
    }
    __syncthreads();

    float sum = 0.0f, cnt = 0.0f;
    for (int i = tid; i < MD; i += 256) {
        if (ious[i] >= 0.5f) {
            float2 a = g_pm[i], b = g_pm[MD + i];
            float2 c = g_pm[2 * MD + i], d = g_pm[3 * MD + i];
            float M = fmaxf(fmaxf(a.x, b.x), fmaxf(c.x, d.x));
            float ns = a.y * expf(a.x - M) + b.y * expf(b.x - M)
                     + c.y * expf(c.x - M) + d.y * expf(d.x - M);
            int l = labels[i];
            l = l < 0 ? 0 : (l >= NCLS ? NCLS - 1 : l);
            float pc = (float)(hist[l] - 1);
            sum += ns / pc;
            cnt += 1.0f;
        }
    }
    ssum[tid] = sum; scnt[tid] = cnt;
    __syncthreads();
    for (int s = 128; s > 0; s >>= 1) {
        if (tid < s) { ssum[tid] += ssum[tid + s]; scnt[tid] += scnt[tid + s]; }
        __syncthreads();
    }
    if (tid == 0) out[0] = ssum[0] / scnt[0];
}

// ---------------------------------------------------------------- launch
extern "C" void kernel_launch(void* const* d_in, const int* in_sizes, int n_in,
                              void* d_out, int out_size) {
    const float* feat   = (const float*)d_in[0];
    const int*   labels = (const int*)  d_in[1];
    const float* ious   = (const float*)d_in[2];
    float*       out    = (float*)d_out;
    (void)in_sizes; (void)n_in; (void)out_size;

    const int smem_bytes = 98304 + 2048;   // A 32K + 2xB 64K + labels 2K
    cudaFuncSetAttribute(k_tensor, cudaFuncAttributeMaxDynamicSharedMemorySize, smem_bytes);

    k_convert<<<MD * KD / (256 * 8), 256>>>(feat);
    k_tensor<<<(MD / 128) * 4, NTHREADS, smem_bytes>>>(labels);
    k_final<<<1, 256>>>(labels, ious, out);
}

// round 8
// speedup vs baseline: 10.4156x; 1.5547x over previous
#include <cuda_runtime.h>
#include <cuda_bf16.h>
#include <math.h>
#include <stdint.h>

// ============================================================================
// GraphCut loss, R7 (resubmit after infra failure): symmetric verification scan.
// sim is symmetric => only upper-triangle block tiles (2080 of 4096) are
// computed. Phase 1 verifies every off-diag s_ij <= seed_i-109 AND
// <= seed_j-109 (bf16 slack 4). If so, every reference exp(s - rowmax)
// underflows to exactly 0 (fp32 exp(x)==0 for x<=-105) => neg sums are
// exactly 0. Any violation bumps g_flagcnt and the full exact R6 kernel
// (k_exact) recomputes everything; k_final branches on the flag.
// ============================================================================

#define MD 8192
#define KD 128
#define NCLS 20
#define NBLK 64                  // 8192/128 row blocks
#define TN 128
#define NQ 2048
#define NTILES (NQ / TN)
#define NTHREADS 512
#define THRESH 105.0f
#define SLACK 109.0f

__device__ __align__(16) __nv_bfloat16 g_featB[(size_t)MD * KD];  // 2MB, *sqrt(5)
__device__ float  g_thr[MD];      // seed_i - SLACK
__device__ int    g_flagcnt;
__device__ float2 g_pm[4 * MD];   // fallback partials

// ---------------------------------------------------------------- helpers
__device__ __forceinline__ uint32_t smem_u32(const void* p) {
    uint32_t a;
    asm("{ .reg .u64 t; cvta.to.shared.u64 t, %1; cvt.u32.u64 %0, t; }" : "=r"(a) : "l"(p));
    return a;
}
#define CP_ASYNC16(dst, src) \
    asm volatile("cp.async.cg.shared.global [%0], [%1], 16;" :: "r"(dst), "l"(src) : "memory")
#define CP_COMMIT() asm volatile("cp.async.commit_group;" ::: "memory")
#define CP_WAIT0()  asm volatile("cp.async.wait_group 0;" ::: "memory")
#define LDSM_X4(r0, r1, r2, r3, a) \
    asm volatile("ldmatrix.sync.aligned.m8n8.x4.shared.b16 {%0,%1,%2,%3}, [%4];" \
                 : "=r"(r0), "=r"(r1), "=r"(r2), "=r"(r3) : "r"(a))
#define MMA16816(c, a0, a1, a2, a3, b0, b1) \
    asm volatile("mma.sync.aligned.m16n8k16.row.col.f32.bf16.bf16.f32 " \
                 "{%0,%1,%2,%3},{%4,%5,%6,%7},{%8,%9},{%0,%1,%2,%3};" \
                 : "+f"((c)[0]), "+f"((c)[1]), "+f"((c)[2]), "+f"((c)[3]) \
                 : "r"(a0), "r"(a1), "r"(a2), "r"(a3), "r"(b0), "r"(b1))

// ---------------------------------------------------------------- convert
__global__ void k_convert(const float* __restrict__ feat) {
    const float SC = 2.23606797749979f;   // sqrt(1/0.2)
    int i = (blockIdx.x * 256 + threadIdx.x) * 8;
    float4 f0 = *(const float4*)&feat[i];
    float4 f1 = *(const float4*)&feat[i + 4];
    union { __nv_bfloat16 h[8]; uint4 u; } U;
    U.h[0] = __float2bfloat16(f0.x * SC); U.h[1] = __float2bfloat16(f0.y * SC);
    U.h[2] = __float2bfloat16(f0.z * SC); U.h[3] = __float2bfloat16(f0.w * SC);
    U.h[4] = __float2bfloat16(f1.x * SC); U.h[5] = __float2bfloat16(f1.y * SC);
    U.h[6] = __float2bfloat16(f1.z * SC); U.h[7] = __float2bfloat16(f1.w * SC);
    *(uint4*)&g_featB[i] = U.u;
}

// ---------------------------------------------------------------- seeds
__global__ void k_seed() {
    int i = blockIdx.x * 256 + threadIdx.x;   // grid 32 -> 8192 rows
    if (i == 0) g_flagcnt = 0;
    const uint4* rp = (const uint4*)&g_featB[(size_t)i * KD];
    float s = 0.0f;
#pragma unroll
    for (int g = 0; g < 16; g++) {
        uint4 u = rp[g];
        uint32_t w[4] = {u.x, u.y, u.z, u.w};
#pragma unroll
        for (int e = 0; e < 4; e++) {
            float lo = __uint_as_float(w[e] << 16);
            float hi = __uint_as_float(w[e] & 0xffff0000u);
            s = fmaf(lo, lo, s);
            s = fmaf(hi, hi, s);
        }
    }
    g_thr[i] = s - SLACK;
}

// ---------------------------------------------------------------- tile fills
__device__ __forceinline__ void fillA(char* A_s, int row0, int tid) {
#pragma unroll
    for (int v = 0; v < 4; v++) {
        int idx = tid + v * NTHREADS;
        int row = idx >> 4, c16 = idx & 15;
        uint4 val = *(const uint4*)&g_featB[(size_t)(row0 + row) * KD + c16 * 8];
        *(uint4*)(A_s + row * 256 + ((c16 ^ (row & 7)) << 4)) = val;
    }
}
__device__ __forceinline__ void fillB_async(uint32_t bu, int row0, int tid) {
#pragma unroll
    for (int v = 0; v < 4; v++) {
        int idx = tid + v * NTHREADS;
        int row = idx >> 4, c16 = idx & 15;
        CP_ASYNC16(bu + row * 256 + ((c16 ^ (row & 7)) << 4),
                   &g_featB[(size_t)(row0 + row) * KD + c16 * 8]);
    }
}

// ---------------------------------------------------------------- phase 1
// 296 CTAs sweep 2080 upper-triangle (I<=J) 128x128 tiles; pure threshold scan.
__global__ void __launch_bounds__(NTHREADS, 2) k_phase1() {
    extern __shared__ char dsm[];
    char*  A_s   = dsm;                       // 32KB
    char*  B_s   = dsm + 32768;               // 2 x 32KB
    float* thrC  = (float*)(dsm + 98304);     // 2 x 128
    float* sThrR = (float*)(dsm + 99328);     // 128
    uint32_t A_u = smem_u32(A_s);
    uint32_t B_u = smem_u32(B_s);
    uint32_t thrC_u = smem_u32(thrC);

    int tid = threadIdx.x, lane = tid & 31, wid = tid >> 5;
    int wm = wid >> 2, wn = wid & 3;
    int c = blockIdx.x;
    int base = c * 7 + (c < 8 ? c : 8);       // 296*7 + 8 = 2080
    int cnt  = 7 + (c < 8 ? 1 : 0);

    int I = 0, tt = base;
    while (tt >= NBLK - I) { tt -= NBLK - I; I++; }
    int J = I + tt;

    // prologue: A(I), sThrR, B(J) + thrC(J) async
    fillA(A_s, I * 128, tid);
    if (tid < 128) sThrR[tid] = g_thr[I * 128 + tid];
    fillB_async(B_u, J * 128, tid);
    if (tid < 32) CP_ASYNC16(thrC_u + tid * 16, &g_thr[J * 128 + tid * 4]);
    CP_COMMIT();

    // ldmatrix per-lane addresses
    int q  = lane >> 3;
    int kh = q >> 1;
    uint32_t aAddr[2]; int aRx[2];
#pragma unroll
    for (int mt = 0; mt < 2; mt++) {
        int row = wm * 32 + mt * 16 + (lane & 7) + ((q & 1) << 3);
        aAddr[mt] = A_u + row * 256;
        aRx[mt]   = row & 7;
    }
    uint32_t bOff[2]; int bRx[2];
#pragma unroll
    for (int bt = 0; bt < 2; bt++) {
        int row = wn * 32 + bt * 16 + (lane & 7) + ((q & 1) << 3);
        bOff[bt] = row * 256;
        bRx[bt]  = row & 7;
    }

    CP_WAIT0();
    __syncthreads();

    for (int it = 0; it < cnt; it++) {
        int nI = I, nJ = J + 1;
        if (nJ == NBLK) { nI = I + 1; nJ = nI; }

        if (it + 1 < cnt) {      // prefetch next B + thrC (overlaps this MMA)
            uint32_t bu = B_u + ((it + 1) & 1) * 32768;
            fillB_async(bu, nJ * 128, tid);
            if (tid < 32)
                CP_ASYNC16(thrC_u + ((it + 1) & 1) * 512 + tid * 16,
                           &g_thr[nJ * 128 + tid * 4]);
            CP_COMMIT();
        }

        uint32_t bu = B_u + (it & 1) * 32768;
        float acc[2][4][4];
#pragma unroll
        for (int a = 0; a < 2; a++)
#pragma unroll
            for (int b = 0; b < 4; b++)
#pragma unroll
                for (int cc = 0; cc < 4; cc++) acc[a][b][cc] = 0.0f;

#pragma unroll
        for (int ks = 0; ks < 8; ks++) {
            uint32_t b0[4], b1[4], a0[4], a1[4];
            LDSM_X4(b0[0], b0[1], b0[2], b0[3], bu + bOff[0] + (((ks * 2 + kh) ^ bRx[0]) << 4));
            LDSM_X4(b1[0], b1[1], b1[2], b1[3], bu + bOff[1] + (((ks * 2 + kh) ^ bRx[1]) << 4));
            LDSM_X4(a0[0], a0[1], a0[2], a0[3], aAddr[0] + (((ks * 2 + kh) ^ aRx[0]) << 4));
            LDSM_X4(a1[0], a1[1], a1[2], a1[3], aAddr[1] + (((ks * 2 + kh) ^ aRx[1]) << 4));
            MMA16816(acc[0][0], a0[0], a0[1], a0[2], a0[3], b0[0], b0[2]);
            MMA16816(acc[0][1], a0[0], a0[1], a0[2], a0[3], b0[1], b0[3]);
            MMA16816(acc[0][2], a0[0], a0[1], a0[2], a0[3], b1[0], b1[2]);
            MMA16816(acc[0][3], a0[0], a0[1], a0[2], a0[3], b1[1], b1[3]);
            MMA16816(acc[1][0], a1[0], a1[1], a1[2], a1[3], b0[0], b0[2]);
            MMA16816(acc[1][1], a1[0], a1[1], a1[2], a1[3], b0[1], b0[3]);
            MMA16816(acc[1][2], a1[0], a1[1], a1[2], a1[3], b1[0], b1[2]);
            MMA16816(acc[1][3], a1[0], a1[1], a1[2], a1[3], b1[1], b1[3]);
        }

        // threshold scan epilogue
        {
            int diag = (I == J);
            const float* tC = thrC + (it & 1) * 128;
            bool f = false;
#pragma unroll
            for (int mt = 0; mt < 2; mt++)
#pragma unroll
                for (int hh = 0; hh < 2; hh++) {
                    int rl = wm * 32 + mt * 16 + hh * 8 + (lane >> 2);
                    float tr = sThrR[rl];
#pragma unroll
                    for (int nt = 0; nt < 4; nt++)
#pragma unroll
                        for (int e = 0; e < 2; e++) {
                            int cl = wn * 32 + nt * 8 + (lane & 3) * 2 + e;
                            float v = acc[mt][nt][hh * 2 + e];
                            bool ex = diag && (rl == cl);
                            f |= (!ex) && ((v > tr) || (v > tC[cl]));
                        }
                }
            if (__any_sync(0xffffffffu, f) && lane == 0) atomicAdd(&g_flagcnt, 1);
        }

        CP_WAIT0();
        __syncthreads();

        if (it + 1 < cnt && nI != I) {       // A block advances (rare)
            fillA(A_s, nI * 128, tid);
            if (tid < 128) sThrR[tid] = g_thr[nI * 128 + tid];
            __syncthreads();
        }
        I = nI; J = nJ;
    }
}

// ---------------------------------------------------------------- exact fallback (R6)
__global__ void __launch_bounds__(NTHREADS, 2)
k_exact(const int* __restrict__ labels) {
    if (g_flagcnt == 0) return;              // phase-1 verified: nothing to do
    extern __shared__ char dsm[];
    __shared__ float2 s_red[128][4];
    __shared__ float  s_seed[128];

    char* A_s  = dsm;
    char* B_s  = dsm + 32768;
    unsigned char* sLbl = (unsigned char*)(dsm + 98304);
    uint32_t A_u = smem_u32(A_s);
    uint32_t B_u = smem_u32(B_s);

    int tid  = threadIdx.x;
    int lane = tid & 31;
    int wid  = tid >> 5;
    int wm   = wid >> 2;
    int wn   = wid & 3;
    int r    = blockIdx.x >> 2;
    int qd   = blockIdx.x & 3;
    int i0   = r * 128;
    int j0   = qd * NQ;

    fillA(A_s, i0, tid);
    fillB_async(B_u, j0, tid);
    CP_COMMIT();
    {
        int4 L = ((const int4*)(labels + j0))[tid];
        ((uint32_t*)sLbl)[tid] = (uint32_t)(L.x & 255) | ((uint32_t)(L.y & 255) << 8)
                               | ((uint32_t)(L.z & 255) << 16) | ((uint32_t)(L.w & 255) << 24);
    }
    {
        int sr = tid >> 2, sq = tid & 3;
        const uint4* rp = (const uint4*)&g_featB[(size_t)(i0 + sr) * KD + sq * 32];
        float sacc = 0.0f;
#pragma unroll
        for (int g = 0; g < 4; g++) {
            uint4 u = rp[g];
            uint32_t w[4] = {u.x, u.y, u.z, u.w};
#pragma unroll
            for (int e = 0; e < 4; e++) {
                float lo = __uint_as_float(w[e] << 16);
                float hi = __uint_as_float(w[e] & 0xffff0000u);
                sacc = fmaf(lo, lo, sacc);
                sacc = fmaf(hi, hi, sacc);
            }
        }
        sacc += __shfl_xor_sync(0xffffffffu, sacc, 1);
        sacc += __shfl_xor_sync(0xffffffffu, sacc, 2);
        if (sq == 0) s_seed[sr] = sacc;
    }

    int myLbl[4];
#pragma unroll
    for (int mt = 0; mt < 2; mt++)
#pragma unroll
        for (int hh = 0; hh < 2; hh++)
            myLbl[mt * 2 + hh] = labels[i0 + wm * 32 + mt * 16 + hh * 8 + (lane >> 2)];

    int q  = lane >> 3;
    int kh = q >> 1;
    uint32_t aAddr[2]; int aRx[2];
#pragma unroll
    for (int mt = 0; mt < 2; mt++) {
        int row = wm * 32 + mt * 16 + (lane & 7) + ((q & 1) << 3);
        aAddr[mt] = A_u + row * 256;
        aRx[mt]   = row & 7;
    }
    uint32_t bOff[2]; int bRx[2];
#pragma unroll
    for (int bt = 0; bt < 2; bt++) {
        int row = wn * 32 + bt * 16 + (lane & 7) + ((q & 1) << 3);
        bOff[bt] = row * 256;
        bRx[bt]  = row & 7;
    }

    CP_WAIT0();
    __syncthreads();

    float mrow[4], prow[4];
#pragma unroll
    for (int mt = 0; mt < 2; mt++)
#pragma unroll
        for (int hh = 0; hh < 2; hh++) {
            mrow[mt * 2 + hh] = s_seed[wm * 32 + mt * 16 + hh * 8 + (lane >> 2)];
            prow[mt * 2 + hh] = 0.0f;
        }

    for (int t = 0; t < NTILES; t++) {
        if (t + 1 < NTILES) {
            fillB_async(B_u + ((t + 1) & 1) * 32768, j0 + (t + 1) * TN, tid);
            CP_COMMIT();
        }

        uint32_t bu = B_u + (t & 1) * 32768;
        float acc[2][4][4];
#pragma unroll
        for (int a = 0; a < 2; a++)
#pragma unroll
            for (int b = 0; b < 4; b++)
#pragma unroll
                for (int cc = 0; cc < 4; cc++) acc[a][b][cc] = 0.0f;

#pragma unroll
        for (int ks = 0; ks < 8; ks++) {
            uint32_t b0[4], b1[4], a0[4], a1[4];
            LDSM_X4(b0[0], b0[1], b0[2], b0[3], bu + bOff[0] + (((ks * 2 + kh) ^ bRx[0]) << 4));
            LDSM_X4(b1[0], b1[1], b1[2], b1[3], bu + bOff[1] + (((ks * 2 + kh) ^ bRx[1]) << 4));
            LDSM_X4(a0[0], a0[1], a0[2], a0[3], aAddr[0] + (((ks * 2 + kh) ^ aRx[0]) << 4));
            LDSM_X4(a1[0], a1[1], a1[2], a1[3], aAddr[1] + (((ks * 2 + kh) ^ aRx[1]) << 4));
            MMA16816(acc[0][0], a0[0], a0[1], a0[2], a0[3], b0[0], b0[2]);
            MMA16816(acc[0][1], a0[0], a0[1], a0[2], a0[3], b0[1], b0[3]);
            MMA16816(acc[0][2], a0[0], a0[1], a0[2], a0[3], b1[0], b1[2]);
            MMA16816(acc[0][3], a0[0], a0[1], a0[2], a0[3], b1[1], b1[3]);
            MMA16816(acc[1][0], a1[0], a1[1], a1[2], a1[3], b0[0], b0[2]);
            MMA16816(acc[1][1], a1[0], a1[1], a1[2], a1[3], b0[1], b0[3]);
            MMA16816(acc[1][2], a1[0], a1[1], a1[2], a1[3], b1[0], b1[2]);
            MMA16816(acc[1][3], a1[0], a1[1], a1[2], a1[3], b1[1], b1[3]);
        }

#pragma unroll
        for (int mt = 0; mt < 2; mt++) {
#pragma unroll
            for (int hh = 0; hh < 2; hh++) {
                int ri = mt * 2 + hh;
                float tmax = acc[mt][0][hh * 2];
                tmax = fmaxf(tmax, acc[mt][0][hh * 2 + 1]);
#pragma unroll
                for (int nt = 1; nt < 4; nt++) {
                    tmax = fmaxf(tmax, acc[mt][nt][hh * 2]);
                    tmax = fmaxf(tmax, acc[mt][nt][hh * 2 + 1]);
                }
                if (__builtin_expect(tmax > mrow[ri] - THRESH, 0)) {
                    float newm = fmaxf(mrow[ri], tmax);
                    prow[ri] *= __expf(mrow[ri] - newm);
                    int ml = myLbl[ri];
#pragma unroll
                    for (int nt = 0; nt < 4; nt++)
#pragma unroll
                        for (int e = 0; e < 2; e++) {
                            float v = acc[mt][nt][hh * 2 + e];
                            if (v > newm - THRESH) {
                                int col = t * TN + wn * 32 + nt * 8 + (lane & 3) * 2 + e;
                                if ((int)sLbl[col] != ml) prow[ri] += __expf(v - newm);
                            }
                        }
                    mrow[ri] = newm;
                }
            }
        }

        CP_WAIT0();
        __syncthreads();
    }

#pragma unroll
    for (int mt = 0; mt < 2; mt++)
#pragma unroll
        for (int hh = 0; hh < 2; hh++) {
            int ri = mt * 2 + hh;
            float m_ = mrow[ri], p_ = prow[ri];
#pragma unroll
            for (int off = 1; off <= 2; off <<= 1) {
                float om = __shfl_xor_sync(0xffffffffu, m_, off);
                float op = __shfl_xor_sync(0xffffffffu, p_, off);
                float M = fmaxf(m_, om);
                p_ = p_ * expf(m_ - M) + op * expf(om - M);
                m_ = M;
            }
            if ((lane & 3) == 0) {
                int rowloc = wm * 32 + mt * 16 + hh * 8 + (lane >> 2);
                s_red[rowloc][wn] = make_float2(m_, p_);
            }
        }
    __syncthreads();
    if (tid < 128) {
        float2 q0 = s_red[tid][0], q1 = s_red[tid][1];
        float2 q2 = s_red[tid][2], q3 = s_red[tid][3];
        float M = fmaxf(fmaxf(q0.x, q1.x), fmaxf(q2.x, q3.x));
        float P = q0.y * expf(q0.x - M) + q1.y * expf(q1.x - M)
                + q2.y * expf(q2.x - M) + q3.y * expf(q3.x - M);
        g_pm[(size_t)qd * MD + i0 + tid] = make_float2(M, P);
    }
}

// ---------------------------------------------------------------- finalize
__global__ void k_final(const int* __restrict__ labels,
                        const float* __restrict__ ious,
                        float* __restrict__ out) {
    __shared__ float ssum[256], scnt[256];
    __shared__ int hist[NCLS];
    int tid = threadIdx.x;
    if (tid < NCLS) hist[tid] = 0;
    __syncthreads();
    for (int i = tid; i < MD; i += 256) {
        int l = labels[i];
        l = l < 0 ? 0 : (l >= NCLS ? NCLS - 1 : l);
        atomicAdd(&hist[l], 1);
    }
    __syncthreads();

    int flg = g_flagcnt;
    float sum = 0.0f, cnt = 0.0f;
    for (int i = tid; i < MD; i += 256) {
        if (ious[i] >= 0.5f) {
            float ns = 0.0f;
            if (flg) {
                float2 a = g_pm[i], b = g_pm[MD + i];
                float2 c = g_pm[2 * MD + i], d = g_pm[3 * MD + i];
                float M = fmaxf(fmaxf(a.x, b.x), fmaxf(c.x, d.x));
                ns = a.y * expf(a.x - M) + b.y * expf(b.x - M)
                   + c.y * expf(c.x - M) + d.y * expf(d.x - M);
            }
            int l = labels[i];
            l = l < 0 ? 0 : (l >= NCLS ? NCLS - 1 : l);
            float pc = (float)(hist[l] - 1);
            sum += ns / pc;
            cnt += 1.0f;
        }
    }
    ssum[tid] = sum; scnt[tid] = cnt;
    __syncthreads();
    for (int s = 128; s > 0; s >>= 1) {
        if (tid < s) { ssum[tid] += ssum[tid + s]; scnt[tid] += scnt[tid + s]; }
        __syncthreads();
    }
    if (tid == 0) out[0] = ssum[0] / scnt[0];
}

// ---------------------------------------------------------------- launch
extern "C" void kernel_launch(void* const* d_in, const int* in_sizes, int n_in,
                              void* d_out, int out_size) {
    const float* feat   = (const float*)d_in[0];
    const int*   labels = (const int*)  d_in[1];
    const float* ious   = (const float*)d_in[2];
    float*       out    = (float*)d_out;
    (void)in_sizes; (void)n_in; (void)out_size;

    const int smem_p1 = 99840;               // A 32K + 2xB 64K + thrC 1K + thrR 0.5K
    const int smem_ex = 98304 + 2048;        // A 32K + 2xB 64K + labels 2K
    cudaFuncSetAttribute(k_phase1, cudaFuncAttributeMaxDynamicSharedMemorySize, smem_p1);
    cudaFuncSetAttribute(k_exact,  cudaFuncAttributeMaxDynamicSharedMemorySize, smem_ex);

    k_convert<<<MD * KD / (256 * 8), 256>>>(feat);
    k_seed<<<MD / 256, 256>>>();
    k_phase1<<<296, NTHREADS, smem_p1>>>();
    k_exact<<<(MD / 128) * 4, NTHREADS, smem_ex>>>(labels);
    k_final<<<1, 256>>>(labels, ious, out);
}